// round 5
// baseline (speedup 1.0000x reference)
#include <cuda_runtime.h>
#include <cuda_bf16.h>

#define BATCH 256
#define NPOS 4
#define NNEG 1024
#define DIM 512
#define CHUNKS 8
#define ROWS_PER_CHUNK (NNEG / CHUNKS)            // 128
#define WARPS_B 8
#define ROWS_PER_WARP (ROWS_PER_CHUNK / WARPS_B)  // 16
#define RBATCH 4
#define NBLOCKS (BATCH * CHUNKS)                  // 2048
#define EPS_F 1e-8f
#define INV_T 10.0f

// Scratch (device allocation forbidden) — fully rewritten each launch.
__device__ float g_pos_sim[BATCH * NPOS];
__device__ float g_exp_part[NBLOCKS];
__device__ int4  g_cnt_part[NBLOCKS];
__device__ unsigned int g_ticket = 0;   // reset by the finalizing block each launch

__device__ __forceinline__ float4 ldcs4(const float4* p) {
    return __ldcs(p);
}

// ---------------------------------------------------------------------------
// Single fused kernel.  One block per (b, chunk); 128 negative rows per block.
//   Prologue : warps 0-3 compute pos_sim[b][*] + 1/||a|| (redundant per chunk;
//              anchor+positives are L2-resident so the redundancy is cheap).
//   Main loop: each warp streams 16 rows, 4 at a time, software-pipelined:
//              FMA consume -> issue next 16 LDG.128 -> shuffle tree + MUFU tail.
//   Epilogue : block partial -> global; last block (atomic ticket) folds all
//              partials deterministically and writes the scalar loss.
// ---------------------------------------------------------------------------
__global__ void __launch_bounds__(256) rrl_fused_kernel(const float* __restrict__ anchor,
                                                        const float* __restrict__ positives,
                                                        const float* __restrict__ negatives,
                                                        float* __restrict__ out) {
    const int b     = blockIdx.x >> 3;
    const int chunk = blockIdx.x & 7;
    const int w     = threadIdx.x >> 5;
    const int lane  = threadIdx.x & 31;

    __shared__ float s_pos[NPOS];
    __shared__ float s_rinv;
    __shared__ float s_exp[WARPS_B];
    __shared__ int   s_cnt[WARPS_B][NPOS];
    __shared__ int   s_last;

    // ---- anchor fragment (register-resident for the whole kernel) ----
    const float4* a4 = reinterpret_cast<const float4*>(anchor + (size_t)b * DIM);
    float4 af[4];
#pragma unroll
    for (int k = 0; k < 4; k++) af[k] = a4[lane + 32 * k];

    // ---- prologue: pos_sim + anchor norm (warps 0-3) ----
    if (w < NPOS) {
        const float4* p4 =
            reinterpret_cast<const float4*>(positives + ((size_t)b * NPOS + w) * DIM);
        float dot = 0.f, sqa = 0.f, sqp = 0.f;
#pragma unroll
        for (int k = 0; k < 4; k++) {
            float4 pv = p4[lane + 32 * k];
            dot += af[k].x * pv.x + af[k].y * pv.y + af[k].z * pv.z + af[k].w * pv.w;
            sqa += af[k].x * af[k].x + af[k].y * af[k].y + af[k].z * af[k].z + af[k].w * af[k].w;
            sqp += pv.x * pv.x + pv.y * pv.y + pv.z * pv.z + pv.w * pv.w;
        }
#pragma unroll
        for (int o = 16; o; o >>= 1) {
            dot += __shfl_xor_sync(0xffffffffu, dot, o);
            sqa += __shfl_xor_sync(0xffffffffu, sqa, o);
            sqp += __shfl_xor_sync(0xffffffffu, sqp, o);
        }
        if (lane == 0) {
            const float na = sqrtf(sqa);
            const float sim = dot / fmaxf(na * sqrtf(sqp), EPS_F);
            s_pos[w] = sim;
            if (w == 0) s_rinv = 1.0f / na;
            if (chunk == 0) g_pos_sim[b * NPOS + w] = sim;
        }
    }
    __syncthreads();

    const float rinv_a = s_rinv;
    const float t0 = s_pos[0], t1 = s_pos[1], t2 = s_pos[2], t3 = s_pos[3];

    float sum_exp = 0.f;
    int c0 = 0, c1 = 0, c2 = 0, c3 = 0;

    // warp w owns rows [w*ROWS_PER_WARP, ...) of this chunk
    const float4* neg_base = reinterpret_cast<const float4*>(
        negatives + ((size_t)b * NNEG + chunk * ROWS_PER_CHUNK + w * ROWS_PER_WARP) * DIM);
    const int ROW4 = DIM / 4;   // 128 float4 per row

    // ---- software-pipelined streaming loop ----
    float4 v[RBATCH][4];
#pragma unroll
    for (int r = 0; r < RBATCH; r++)
#pragma unroll
        for (int k = 0; k < 4; k++)
            v[r][k] = ldcs4(neg_base + (size_t)r * ROW4 + lane + 32 * k);

    for (int i = 0; i < ROWS_PER_WARP; i += RBATCH) {
        // 1) consume v into per-lane partials (frees the v registers)
        float dot[RBATCH], sq[RBATCH];
#pragma unroll
        for (int r = 0; r < RBATCH; r++) {
            float d = 0.f, s = 0.f;
#pragma unroll
            for (int k = 0; k < 4; k++) {
                d += af[k].x * v[r][k].x + af[k].y * v[r][k].y +
                     af[k].z * v[r][k].z + af[k].w * v[r][k].w;
                s += v[r][k].x * v[r][k].x + v[r][k].y * v[r][k].y +
                     v[r][k].z * v[r][k].z + v[r][k].w * v[r][k].w;
            }
            dot[r] = d;
            sq[r]  = s;
        }

        // 2) issue next batch's loads NOW — in flight through the whole tail
        if (i + RBATCH < ROWS_PER_WARP) {
#pragma unroll
            for (int r = 0; r < RBATCH; r++)
#pragma unroll
                for (int k = 0; k < 4; k++)
                    v[r][k] = ldcs4(neg_base + (size_t)(i + RBATCH + r) * ROW4 + lane + 32 * k);
        }

        // 3) interleaved butterfly reductions (8 independent chains per level)
#pragma unroll
        for (int o = 16; o; o >>= 1) {
#pragma unroll
            for (int r = 0; r < RBATCH; r++) {
                dot[r] += __shfl_xor_sync(0xffffffffu, dot[r], o);
                sq[r]  += __shfl_xor_sync(0xffffffffu, sq[r], o);
            }
        }

        // 4) sim tail
#pragma unroll
        for (int r = 0; r < RBATCH; r++) {
            const float sim = dot[r] * (rinv_a * rsqrtf(fmaxf(sq[r], EPS_F * EPS_F)));
            sum_exp += __expf(sim * INV_T);
            c0 += (sim > t0);
            c1 += (sim > t1);
            c2 += (sim > t2);
            c3 += (sim > t3);
        }
    }

    // ---- block reduction of partials ----
    if (lane == 0) {
        s_exp[w]    = sum_exp;
        s_cnt[w][0] = c0; s_cnt[w][1] = c1; s_cnt[w][2] = c2; s_cnt[w][3] = c3;
    }
    __syncthreads();
    if (threadIdx.x == 0) {
        float se = 0.f;
        int k0 = 0, k1 = 0, k2 = 0, k3 = 0;
#pragma unroll
        for (int j = 0; j < WARPS_B; j++) {
            se += s_exp[j];
            k0 += s_cnt[j][0]; k1 += s_cnt[j][1]; k2 += s_cnt[j][2]; k3 += s_cnt[j][3];
        }
        g_exp_part[blockIdx.x] = se;
        g_cnt_part[blockIdx.x] = make_int4(k0, k1, k2, k3);
        __threadfence();                       // partials visible before ticket
        const unsigned int t = atomicAdd(&g_ticket, 1u);
        s_last = (t == NBLOCKS - 1u) ? 1 : 0;
    }
    __syncthreads();

    // ---- last block finalizes (deterministic fixed-order fold) ----
    if (s_last) {
        const int bb = threadIdx.x;            // thread = batch index

        float se = 0.f;
        int cnt[NPOS] = {0, 0, 0, 0};
#pragma unroll
        for (int c = 0; c < CHUNKS; c++) {
            const int idx = bb * CHUNKS + c;
            se += g_exp_part[idx];
            const int4 k = g_cnt_part[idx];
            cnt[0] += k.x; cnt[1] += k.y; cnt[2] += k.z; cnt[3] += k.w;
        }

        float ps[NPOS], ep[NPOS];
        float denom = se;
#pragma unroll
        for (int p = 0; p < NPOS; p++) {
            ps[p] = g_pos_sim[bb * NPOS + p];
            ep[p] = expf(ps[p] * INV_T);
            denom += ep[p];
        }

        float err = 0.f, psum = 0.f;
#pragma unroll
        for (int p = 0; p < NPOS; p++) {
            int rank = cnt[p];
#pragma unroll
            for (int q = 0; q < NPOS; q++) {
                if (ps[q] > ps[p]) rank++;
                else if (q < p && ps[q] == ps[p]) rank++;
            }
            err  += (ep[p] / denom) / (float)(rank + 1);
            psum += ps[p];
        }

        __shared__ float s_err[256];
        __shared__ float s_psum[256];
        s_err[bb]  = err;
        s_psum[bb] = psum;
        __syncthreads();
        for (int off = 128; off; off >>= 1) {
            if (bb < off) {
                s_err[bb]  += s_err[bb + off];
                s_psum[bb] += s_psum[bb + off];
            }
            __syncthreads();
        }
        if (bb == 0) {
            out[0] = -s_err[0] / (float)BATCH +
                     0.3f * (1.0f - s_psum[0] / (float)(BATCH * NPOS));
            g_ticket = 0;                      // re-arm for next (graph) replay
        }
    }
}

// ---------------------------------------------------------------------------
extern "C" void kernel_launch(void* const* d_in, const int* in_sizes, int n_in,
                              void* d_out, int out_size) {
    const float* anchor    = (const float*)d_in[0];
    const float* positives = (const float*)d_in[1];
    const float* negatives = (const float*)d_in[2];

    rrl_fused_kernel<<<NBLOCKS, 256>>>(anchor, positives, negatives, (float*)d_out);
}

// round 6
// speedup vs baseline: 1.0215x; 1.0215x over previous
#include <cuda_runtime.h>
#include <cuda_bf16.h>

#define BATCH 256
#define NPOS 4
#define NNEG 1024
#define DIM 512
#define CHUNKS 4
#define ROWS_PER_CHUNK (NNEG / CHUNKS)            // 256
#define WARPS_B 8
#define ROWS_PER_WARP (ROWS_PER_CHUNK / WARPS_B)  // 32
#define RBATCH 4
#define NBLOCKS (BATCH * CHUNKS)                  // 1024
#define EPS_F 1e-8f
#define INV_T 10.0f

// Scratch (device allocation forbidden) — fully rewritten each launch.
__device__ float g_pos_sim[BATCH * NPOS];
__device__ float g_exp_part[NBLOCKS];
__device__ int4  g_cnt_part[NBLOCKS];
__device__ unsigned int g_ticket = 0;   // reset by the finalizing block each launch

__device__ __forceinline__ float4 ldcs4(const float4* p) {
    return __ldcs(p);
}

// ---------------------------------------------------------------------------
// Single fused kernel.  One block per (b, chunk); 256 negative rows per block.
//   Order of operations per warp:
//     1) issue first 16 negative LDG.128 (the big streaming loads) FIRST
//     2) prologue (anchor re-load, pos_sim, 1/||a||) runs while they fly
//     3) software-pipelined main loop: consume -> issue next 16 -> shuffles/tail
//   Epilogue: block partial -> global; last block (atomic ticket) folds all
//   partials in a fixed deterministic order and writes the scalar loss.
// ---------------------------------------------------------------------------
__global__ void __launch_bounds__(256) rrl_fused_kernel(const float* __restrict__ anchor,
                                                        const float* __restrict__ positives,
                                                        const float* __restrict__ negatives,
                                                        float* __restrict__ out) {
    const int b     = blockIdx.x >> 2;
    const int chunk = blockIdx.x & 3;
    const int w     = threadIdx.x >> 5;
    const int lane  = threadIdx.x & 31;

    __shared__ float s_pos[NPOS];
    __shared__ float s_rinv;
    __shared__ float s_exp[WARPS_B];
    __shared__ int   s_cnt[WARPS_B][NPOS];
    __shared__ int   s_last;

    const int ROW4 = DIM / 4;   // 128 float4 per row
    const float4* neg_base = reinterpret_cast<const float4*>(
        negatives + ((size_t)b * NNEG + chunk * ROWS_PER_CHUNK + w * ROWS_PER_WARP) * DIM);

    // ---- (1) issue the first streaming batch IMMEDIATELY ----
    float4 v[RBATCH][4];
#pragma unroll
    for (int r = 0; r < RBATCH; r++)
#pragma unroll
        for (int k = 0; k < 4; k++)
            v[r][k] = ldcs4(neg_base + (size_t)r * ROW4 + lane + 32 * k);

    // ---- (2) prologue overlapped with the in-flight loads ----
    const float4* a4 = reinterpret_cast<const float4*>(anchor + (size_t)b * DIM);
    float4 af[4];
#pragma unroll
    for (int k = 0; k < 4; k++) af[k] = a4[lane + 32 * k];

    if (w < NPOS) {
        const float4* p4 =
            reinterpret_cast<const float4*>(positives + ((size_t)b * NPOS + w) * DIM);
        float dot = 0.f, sqa = 0.f, sqp = 0.f;
#pragma unroll
        for (int k = 0; k < 4; k++) {
            float4 pv = p4[lane + 32 * k];
            dot += af[k].x * pv.x + af[k].y * pv.y + af[k].z * pv.z + af[k].w * pv.w;
            sqa += af[k].x * af[k].x + af[k].y * af[k].y + af[k].z * af[k].z + af[k].w * af[k].w;
            sqp += pv.x * pv.x + pv.y * pv.y + pv.z * pv.z + pv.w * pv.w;
        }
#pragma unroll
        for (int o = 16; o; o >>= 1) {
            dot += __shfl_xor_sync(0xffffffffu, dot, o);
            sqa += __shfl_xor_sync(0xffffffffu, sqa, o);
            sqp += __shfl_xor_sync(0xffffffffu, sqp, o);
        }
        if (lane == 0) {
            const float na = sqrtf(sqa);
            const float sim = dot / fmaxf(na * sqrtf(sqp), EPS_F);
            s_pos[w] = sim;
            if (w == 0) s_rinv = 1.0f / na;
            if (chunk == 0) g_pos_sim[b * NPOS + w] = sim;
        }
    }
    __syncthreads();

    const float rinv_a = s_rinv;
    const float t0 = s_pos[0], t1 = s_pos[1], t2 = s_pos[2], t3 = s_pos[3];

    float sum_exp = 0.f;
    int c0 = 0, c1 = 0, c2 = 0, c3 = 0;

    // ---- (3) software-pipelined streaming loop ----
    for (int i = 0; i < ROWS_PER_WARP; i += RBATCH) {
        // consume v into per-lane partials (frees the v registers)
        float dot[RBATCH], sq[RBATCH];
#pragma unroll
        for (int r = 0; r < RBATCH; r++) {
            float d = 0.f, s = 0.f;
#pragma unroll
            for (int k = 0; k < 4; k++) {
                d += af[k].x * v[r][k].x + af[k].y * v[r][k].y +
                     af[k].z * v[r][k].z + af[k].w * v[r][k].w;
                s += v[r][k].x * v[r][k].x + v[r][k].y * v[r][k].y +
                     v[r][k].z * v[r][k].z + v[r][k].w * v[r][k].w;
            }
            dot[r] = d;
            sq[r]  = s;
        }

        // issue next batch's loads NOW — in flight through the whole tail
        if (i + RBATCH < ROWS_PER_WARP) {
#pragma unroll
            for (int r = 0; r < RBATCH; r++)
#pragma unroll
                for (int k = 0; k < 4; k++)
                    v[r][k] = ldcs4(neg_base + (size_t)(i + RBATCH + r) * ROW4 + lane + 32 * k);
        }

        // interleaved butterfly reductions (8 independent chains per level)
#pragma unroll
        for (int o = 16; o; o >>= 1) {
#pragma unroll
            for (int r = 0; r < RBATCH; r++) {
                dot[r] += __shfl_xor_sync(0xffffffffu, dot[r], o);
                sq[r]  += __shfl_xor_sync(0xffffffffu, sq[r], o);
            }
        }

        // sim tail
#pragma unroll
        for (int r = 0; r < RBATCH; r++) {
            const float sim = dot[r] * (rinv_a * rsqrtf(fmaxf(sq[r], EPS_F * EPS_F)));
            sum_exp += __expf(sim * INV_T);
            c0 += (sim > t0);
            c1 += (sim > t1);
            c2 += (sim > t2);
            c3 += (sim > t3);
        }
    }

    // ---- block reduction of partials ----
    if (lane == 0) {
        s_exp[w]    = sum_exp;
        s_cnt[w][0] = c0; s_cnt[w][1] = c1; s_cnt[w][2] = c2; s_cnt[w][3] = c3;
    }
    __syncthreads();
    if (threadIdx.x == 0) {
        float se = 0.f;
        int k0 = 0, k1 = 0, k2 = 0, k3 = 0;
#pragma unroll
        for (int j = 0; j < WARPS_B; j++) {
            se += s_exp[j];
            k0 += s_cnt[j][0]; k1 += s_cnt[j][1]; k2 += s_cnt[j][2]; k3 += s_cnt[j][3];
        }
        g_exp_part[blockIdx.x] = se;
        g_cnt_part[blockIdx.x] = make_int4(k0, k1, k2, k3);
        __threadfence();                       // partials visible before ticket
        const unsigned int t = atomicAdd(&g_ticket, 1u);
        s_last = (t == NBLOCKS - 1u) ? 1 : 0;
    }
    __syncthreads();

    // ---- last block finalizes (deterministic fixed-order fold) ----
    if (s_last) {
        const int bb = threadIdx.x;            // thread = batch index

        float se = 0.f;
        int cnt[NPOS] = {0, 0, 0, 0};
#pragma unroll
        for (int c = 0; c < CHUNKS; c++) {
            const int idx = bb * CHUNKS + c;
            se += g_exp_part[idx];
            const int4 k = g_cnt_part[idx];
            cnt[0] += k.x; cnt[1] += k.y; cnt[2] += k.z; cnt[3] += k.w;
        }

        float ps[NPOS], ep[NPOS];
        float denom = se;
#pragma unroll
        for (int p = 0; p < NPOS; p++) {
            ps[p] = g_pos_sim[bb * NPOS + p];
            ep[p] = expf(ps[p] * INV_T);
            denom += ep[p];
        }

        float err = 0.f, psum = 0.f;
#pragma unroll
        for (int p = 0; p < NPOS; p++) {
            int rank = cnt[p];
#pragma unroll
            for (int q = 0; q < NPOS; q++) {
                if (ps[q] > ps[p]) rank++;
                else if (q < p && ps[q] == ps[p]) rank++;
            }
            err  += (ep[p] / denom) / (float)(rank + 1);
            psum += ps[p];
        }

        __shared__ float s_err[256];
        __shared__ float s_psum[256];
        s_err[bb]  = err;
        s_psum[bb] = psum;
        __syncthreads();
        for (int off = 128; off; off >>= 1) {
            if (bb < off) {
                s_err[bb]  += s_err[bb + off];
                s_psum[bb] += s_psum[bb + off];
            }
            __syncthreads();
        }
        if (bb == 0) {
            out[0] = -s_err[0] / (float)BATCH +
                     0.3f * (1.0f - s_psum[0] / (float)(BATCH * NPOS));
            g_ticket = 0;                      // re-arm for next (graph) replay
        }
    }
}

// ---------------------------------------------------------------------------
extern "C" void kernel_launch(void* const* d_in, const int* in_sizes, int n_in,
                              void* d_out, int out_size) {
    const float* anchor    = (const float*)d_in[0];
    const float* positives = (const float*)d_in[1];
    const float* negatives = (const float*)d_in[2];

    rrl_fused_kernel<<<NBLOCKS, 256>>>(anchor, positives, negatives, (float*)d_out);
}